// round 1
// baseline (speedup 1.0000x reference)
#include <cuda_runtime.h>

#define LEAK  0.1f
#define BNEPS 1e-5f

// Problem constants
#define NB   64          // batch
#define HW   361         // 19*19
#define H19  19
#define C2IN 1280        // concat channels
#define C2K  11520       // 1280*9
#define KO   600         // 20*30

// ---------------- scratch (device globals; no runtime allocation) ----------
__device__ float g_w1t[512 * 64];          // transposed conv1 weights [k][co]
__device__ float g_s1[64],  g_h1[64];      // conv1 BN scale/shift
__device__ float g_s2[1024], g_h2[1024];   // conv2 BN scale/shift
__device__ float g_rwp[KO * 1024];         // repacked reweight [m][c], stride 1024
__device__ float g_cb[KO];                 // bias per m
__device__ float g_catx[(size_t)NB * 256 * HW];   // reorg(conv1) output
__device__ float g_pre [(size_t)NB * 1024 * HW];  // conv2 output (post BN+leaky)

// ---------------- prep: weight transpose, BN folding, reweight repack ------
__global__ void prep_kernel(const float* __restrict__ w1,
                            const float* __restrict__ g1, const float* __restrict__ b1,
                            const float* __restrict__ m1, const float* __restrict__ v1,
                            const float* __restrict__ g2, const float* __restrict__ b2,
                            const float* __restrict__ m2, const float* __restrict__ v2,
                            const float* __restrict__ rw)
{
    int i = blockIdx.x * blockDim.x + threadIdx.x;
    if (i < 512 * 64) {                       // w1t[k][co] = w1[co][k]
        int k = i >> 6, co = i & 63;
        g_w1t[i] = w1[co * 512 + k];
    }
    if (i < KO * 1024) {                      // rwp[m][c] = rw[m][c] (drop bias col)
        int m = i >> 10, c = i & 1023;
        g_rwp[i] = rw[m * 1025 + c];
    }
    if (i < KO)   g_cb[i] = rw[i * 1025 + 1024];
    if (i < 64)   { float s = g1[i] * rsqrtf(v1[i] + BNEPS); g_s1[i] = s; g_h1[i] = b1[i] - m1[i] * s; }
    if (i < 1024) { float s = g2[i] * rsqrtf(v2[i] + BNEPS); g_s2[i] = s; g_h2[i] = b2[i] - m2[i] * s; }
}

// ---------------- conv1 (1x1, 512->64) + BN + leaky + reorg(2) -------------
// Block: 16 pixels x 64 co, 256 threads, thread = (co, 4-pixel group).
__global__ __launch_bounds__(256) void conv1_kernel(const float* __restrict__ feat1)
{
    __shared__ __align__(16) float s_in[512][16];   // [k][pixel]   32 KB
    __shared__ float s_w[64][64];                   // [k_local][co] 16 KB

    const int b    = blockIdx.y;
    const int base = blockIdx.x * 16;               // pixel tile base (of 1444)
    const float* f = feat1 + (size_t)b * 512 * 1444;

    for (int idx = threadIdx.x; idx < 512 * 16; idx += 256) {
        int p = idx & 15, k = idx >> 4;
        int pix = base + p;
        s_in[k][p] = (pix < 1444) ? f[k * 1444 + pix] : 0.f;
    }

    const int co = threadIdx.x & 63;
    const int pq = threadIdx.x >> 6;                // 0..3 -> pixels pq*4..pq*4+3
    float acc[4] = {0.f, 0.f, 0.f, 0.f};

    for (int kc = 0; kc < 512; kc += 64) {
        __syncthreads();
        for (int idx = threadIdx.x; idx < 64 * 64; idx += 256)
            s_w[idx >> 6][idx & 63] = g_w1t[(kc + (idx >> 6)) * 64 + (idx & 63)];
        __syncthreads();
        #pragma unroll
        for (int kk = 0; kk < 64; kk++) {
            float  w = s_w[kk][co];
            float4 v = *(const float4*)&s_in[kc + kk][pq * 4];
            acc[0] += v.x * w; acc[1] += v.y * w;
            acc[2] += v.z * w; acc[3] += v.w * w;
        }
    }

    const float s = g_s1[co], hh = g_h1[co];
    #pragma unroll
    for (int j = 0; j < 4; j++) {
        int pix = base + pq * 4 + j;
        if (pix < 1444) {
            float y = acc[j] * s + hh;
            y = (y > 0.f) ? y : LEAK * y;
            int h38 = pix / 38, w38 = pix - h38 * 38;
            int cc  = ((h38 & 1) * 2 + (w38 & 1)) * 64 + co;   // reorg channel
            g_catx[((size_t)b * 256 + cc) * HW + (h38 >> 1) * H19 + (w38 >> 1)] = y;
        }
    }
}

// ---------------- conv2 (3x3 pad1, 1280->1024) + BN + leaky ----------------
// Implicit GEMM: M=1024(co) K=11520 N=361(px) per image.
// Tile 128x64x16, 256 threads, 8x4 micro-tile. Concat virtualized in gather.
__global__ __launch_bounds__(256) void conv2_kernel(const float* __restrict__ feat0,
                                                    const float* __restrict__ w2)
{
    const int b   = blockIdx.z;
    const int co0 = blockIdx.y * 128;
    const int px0 = blockIdx.x * 64;

    __shared__ __align__(16) float As[16][128];
    __shared__ __align__(16) float Bs[16][64];

    const int tid = threadIdx.x;
    const int tx  = tid & 15;     // col group (4 px)
    const int ty  = tid >> 4;     // row group (8 co)

    float acc[8][4];
    #pragma unroll
    for (int i = 0; i < 8; i++)
        #pragma unroll
        for (int j = 0; j < 4; j++) acc[i][j] = 0.f;

    // A-load mapping: 2 threads per co row, 8 floats (2x float4) each
    const int a_row  = tid >> 1;
    const int a_koff = (tid & 1) * 8;
    const float* w2row = w2 + (size_t)(co0 + a_row) * C2K + a_koff;

    // B-load mapping: thread loads 4 k-rows for one pixel column
    const int b_px = tid & 63;
    const int b_k0 = tid >> 6;          // 0..3
    const int pixel_b = px0 + b_px;
    const int oh = pixel_b / H19;
    const int ow = pixel_b - oh * H19;
    const bool px_ok = (pixel_b < HW);

    const float* catx_b = g_catx + (size_t)b * 256 * HW;
    const float* f0_b   = feat0  + (size_t)b * 1024 * HW;

    for (int k0 = 0; k0 < C2K; k0 += 16) {
        float4 av0 = *(const float4*)(w2row + k0);
        float4 av1 = *(const float4*)(w2row + k0 + 4);

        float bv[4];
        #pragma unroll
        for (int u = 0; u < 4; u++) {
            int k  = k0 + b_k0 + 4 * u;
            int c  = k / 9;
            int r  = k - c * 9;
            int dy = r / 3, dx = r - dy * 3;
            int ih = oh + dy - 1, iw = ow + dx - 1;
            float v = 0.f;
            if (px_ok && (unsigned)ih < 19u && (unsigned)iw < 19u) {
                int sp = ih * H19 + iw;
                v = (c < 256) ? catx_b[c * HW + sp] : f0_b[(c - 256) * HW + sp];
            }
            bv[u] = v;
        }

        __syncthreads();
        As[a_koff + 0][a_row] = av0.x; As[a_koff + 1][a_row] = av0.y;
        As[a_koff + 2][a_row] = av0.z; As[a_koff + 3][a_row] = av0.w;
        As[a_koff + 4][a_row] = av1.x; As[a_koff + 5][a_row] = av1.y;
        As[a_koff + 6][a_row] = av1.z; As[a_koff + 7][a_row] = av1.w;
        #pragma unroll
        for (int u = 0; u < 4; u++) Bs[b_k0 + 4 * u][b_px] = bv[u];
        __syncthreads();

        #pragma unroll
        for (int kk = 0; kk < 16; kk++) {
            float4 a0 = *(const float4*)&As[kk][ty * 8];
            float4 a1 = *(const float4*)&As[kk][ty * 8 + 4];
            float4 bb = *(const float4*)&Bs[kk][tx * 4];
            float ar[8] = {a0.x, a0.y, a0.z, a0.w, a1.x, a1.y, a1.z, a1.w};
            float br[4] = {bb.x, bb.y, bb.z, bb.w};
            #pragma unroll
            for (int i = 0; i < 8; i++)
                #pragma unroll
                for (int j = 0; j < 4; j++)
                    acc[i][j] += ar[i] * br[j];
        }
    }

    #pragma unroll
    for (int i = 0; i < 8; i++) {
        int co = co0 + ty * 8 + i;
        float s = g_s2[co], hh = g_h2[co];
        #pragma unroll
        for (int j = 0; j < 4; j++) {
            int pixel = px0 + tx * 4 + j;
            if (pixel < HW) {
                float y = acc[i][j] * s + hh;
                y = (y > 0.f) ? y : LEAK * y;
                g_pre[((size_t)b * 1024 + co) * HW + pixel] = y;
            }
        }
    }
}

// ---------------- detection head: C[600x361] = RW[600x1024] x pre[1024x361] + cb
__global__ __launch_bounds__(256) void det_kernel(float* __restrict__ out)
{
    const int b   = blockIdx.z;
    const int m0  = blockIdx.y * 128;
    const int px0 = blockIdx.x * 64;

    __shared__ __align__(16) float As[16][128];
    __shared__ __align__(16) float Bs[16][64];

    const int tid = threadIdx.x;
    const int tx  = tid & 15;
    const int ty  = tid >> 4;

    float acc[8][4];
    #pragma unroll
    for (int i = 0; i < 8; i++)
        #pragma unroll
        for (int j = 0; j < 4; j++) acc[i][j] = 0.f;

    const int a_row  = tid >> 1;
    const int a_koff = (tid & 1) * 8;
    const int m = m0 + a_row;
    const float* arow = g_rwp + (size_t)m * 1024 + a_koff;
    const bool m_ok = (m < KO);

    const int b_px = tid & 63;
    const int b_k0 = tid >> 6;
    const int pixel_b = px0 + b_px;
    const bool px_ok = (pixel_b < HW);
    const float* pre_b = g_pre + (size_t)b * 1024 * HW;

    for (int k0 = 0; k0 < 1024; k0 += 16) {
        float4 av0 = make_float4(0.f, 0.f, 0.f, 0.f), av1 = av0;
        if (m_ok) {
            av0 = *(const float4*)(arow + k0);
            av1 = *(const float4*)(arow + k0 + 4);
        }
        float bv[4];
        #pragma unroll
        for (int u = 0; u < 4; u++) {
            int c = k0 + b_k0 + 4 * u;
            bv[u] = px_ok ? pre_b[c * HW + pixel_b] : 0.f;
        }

        __syncthreads();
        As[a_koff + 0][a_row] = av0.x; As[a_koff + 1][a_row] = av0.y;
        As[a_koff + 2][a_row] = av0.z; As[a_koff + 3][a_row] = av0.w;
        As[a_koff + 4][a_row] = av1.x; As[a_koff + 5][a_row] = av1.y;
        As[a_koff + 6][a_row] = av1.z; As[a_koff + 7][a_row] = av1.w;
        #pragma unroll
        for (int u = 0; u < 4; u++) Bs[b_k0 + 4 * u][b_px] = bv[u];
        __syncthreads();

        #pragma unroll
        for (int kk = 0; kk < 16; kk++) {
            float4 a0 = *(const float4*)&As[kk][ty * 8];
            float4 a1 = *(const float4*)&As[kk][ty * 8 + 4];
            float4 bb = *(const float4*)&Bs[kk][tx * 4];
            float ar[8] = {a0.x, a0.y, a0.z, a0.w, a1.x, a1.y, a1.z, a1.w};
            float br[4] = {bb.x, bb.y, bb.z, bb.w};
            #pragma unroll
            for (int i = 0; i < 8; i++)
                #pragma unroll
                for (int j = 0; j < 4; j++)
                    acc[i][j] += ar[i] * br[j];
        }
    }

    #pragma unroll
    for (int i = 0; i < 8; i++) {
        int mm = m0 + ty * 8 + i;
        if (mm < KO) {
            float cb = g_cb[mm];
            #pragma unroll
            for (int j = 0; j < 4; j++) {
                int pixel = px0 + tx * 4 + j;
                if (pixel < HW)
                    out[(size_t)b * (KO * HW) + (size_t)mm * HW + pixel] = acc[i][j] + cb;
            }
        }
    }
}

// ---------------- launch ----------------------------------------------------
extern "C" void kernel_launch(void* const* d_in, const int* in_sizes, int n_in,
                              void* d_out, int out_size)
{
    const float* feat0 = (const float*)d_in[0];
    const float* feat1 = (const float*)d_in[1];
    const float* w1    = (const float*)d_in[2];
    const float* g1    = (const float*)d_in[3];
    const float* b1    = (const float*)d_in[4];
    const float* m1    = (const float*)d_in[5];
    const float* v1    = (const float*)d_in[6];
    const float* w2    = (const float*)d_in[7];
    const float* g2    = (const float*)d_in[8];
    const float* b2    = (const float*)d_in[9];
    const float* m2    = (const float*)d_in[10];
    const float* v2    = (const float*)d_in[11];
    const float* rw    = (const float*)d_in[12];
    float* out = (float*)d_out;

    prep_kernel<<<2400, 256>>>(w1, g1, b1, m1, v1, g2, b2, m2, v2, rw);
    conv1_kernel<<<dim3(91, NB), 256>>>(feat1);           // ceil(1444/16)=91
    conv2_kernel<<<dim3(6, 8, NB), 256>>>(feat0, w2);     // ceil(361/64)=6, 1024/128=8
    det_kernel  <<<dim3(6, 5, NB), 256>>>(out);           // ceil(600/128)=5
}

// round 4
// speedup vs baseline: 2.0429x; 2.0429x over previous
#include <cuda_runtime.h>
#include <cuda_bf16.h>

#define LEAK  0.1f
#define BNEPS 1e-5f

#define NB    64
#define HW    361            // 19*19
#define H19   19
#define C2K   11520          // 1280*9
#define KO    600
#define KOP   640            // padded to 5*128
#define NPIX  (NB * HW)      // 23104 global pixels

// ---------------- device scratch ----------------
__device__ float g_w1t[512 * 64];
__device__ float g_s1[64],  g_h1[64];
__device__ float g_s2[1024], g_h2[1024];
__device__ float g_cb[KO];
__device__ float g_catx[(size_t)NB * 256 * HW];
__device__ float g_pre [(size_t)NB * 1024 * HW];

__device__ __align__(16) __nv_bfloat16 g_w2h[(size_t)1024 * C2K];
__device__ __align__(16) __nv_bfloat16 g_w2l[(size_t)1024 * C2K];
__device__ __align__(16) __nv_bfloat16 g_rwh[(size_t)KOP * 1024];
__device__ __align__(16) __nv_bfloat16 g_rwl[(size_t)KOP * 1024];

// ---------------- prep: BN fold, transposes, bf16 hi/lo splits --------------
__global__ void prep_kernel(const float* __restrict__ w1,
                            const float* __restrict__ g1, const float* __restrict__ b1,
                            const float* __restrict__ m1, const float* __restrict__ v1,
                            const float* __restrict__ g2, const float* __restrict__ b2,
                            const float* __restrict__ m2, const float* __restrict__ v2,
                            const float* __restrict__ rw, const float* __restrict__ w2)
{
    long long i = (long long)blockIdx.x * blockDim.x + threadIdx.x;
    if (i < (long long)1024 * C2K) {
        float x = w2[i];
        __nv_bfloat16 h = __float2bfloat16_rn(x);
        g_w2h[i] = h;
        g_w2l[i] = __float2bfloat16_rn(x - __bfloat162float(h));
    }
    if (i < (long long)KOP * 1024) {
        int m = (int)(i >> 10), c = (int)(i & 1023);
        float x = (m < KO) ? rw[m * 1025 + c] : 0.f;
        __nv_bfloat16 h = __float2bfloat16_rn(x);
        g_rwh[i] = h;
        g_rwl[i] = __float2bfloat16_rn(x - __bfloat162float(h));
    }
    if (i < 512 * 64) {
        int k = (int)(i >> 6), co = (int)(i & 63);
        g_w1t[i] = w1[co * 512 + k];
    }
    if (i < KO)   g_cb[i] = rw[i * 1025 + 1024];
    if (i < 64)   { float s = g1[i] * rsqrtf(v1[i] + BNEPS); g_s1[i] = s; g_h1[i] = b1[i] - m1[i] * s; }
    if (i < 1024) { float s = g2[i] * rsqrtf(v2[i] + BNEPS); g_s2[i] = s; g_h2[i] = b2[i] - m2[i] * s; }
}

// ---------------- conv1 (1x1, 512->64) + BN + leaky + reorg(2) --------------
__global__ __launch_bounds__(256) void conv1_kernel(const float* __restrict__ feat1)
{
    __shared__ __align__(16) float s_in[512][16];
    __shared__ float s_w[64][64];

    const int b    = blockIdx.y;
    const int base = blockIdx.x * 16;
    const float* f = feat1 + (size_t)b * 512 * 1444;

    for (int idx = threadIdx.x; idx < 512 * 16; idx += 256) {
        int p = idx & 15, k = idx >> 4;
        int pix = base + p;
        s_in[k][p] = (pix < 1444) ? f[k * 1444 + pix] : 0.f;
    }

    const int co = threadIdx.x & 63;
    const int pq = threadIdx.x >> 6;
    float acc[4] = {0.f, 0.f, 0.f, 0.f};

    for (int kc = 0; kc < 512; kc += 64) {
        __syncthreads();
        for (int idx = threadIdx.x; idx < 64 * 64; idx += 256)
            s_w[idx >> 6][idx & 63] = g_w1t[(kc + (idx >> 6)) * 64 + (idx & 63)];
        __syncthreads();
        #pragma unroll
        for (int kk = 0; kk < 64; kk++) {
            float  w = s_w[kk][co];
            float4 v = *(const float4*)&s_in[kc + kk][pq * 4];
            acc[0] += v.x * w; acc[1] += v.y * w;
            acc[2] += v.z * w; acc[3] += v.w * w;
        }
    }

    const float s = g_s1[co], hh = g_h1[co];
    #pragma unroll
    for (int j = 0; j < 4; j++) {
        int pix = base + pq * 4 + j;
        if (pix < 1444) {
            float y = acc[j] * s + hh;
            y = (y > 0.f) ? y : LEAK * y;
            int h38 = pix / 38, w38 = pix - h38 * 38;
            int cc  = ((h38 & 1) * 2 + (w38 & 1)) * 64 + co;
            g_catx[((size_t)b * 256 + cc) * HW + (h38 >> 1) * H19 + (w38 >> 1)] = y;
        }
    }
}

// ---------------- mma.sync helper (bf16, fp32 accum) ------------------------
__device__ __forceinline__ void mma16816(float* d, const unsigned* a, const unsigned* b)
{
    asm volatile(
        "mma.sync.aligned.m16n8k16.row.col.f32.bf16.bf16.f32 "
        "{%0,%1,%2,%3},{%4,%5,%6,%7},{%8,%9},{%0,%1,%2,%3};"
        : "+f"(d[0]), "+f"(d[1]), "+f"(d[2]), "+f"(d[3])
        : "r"(a[0]), "r"(a[1]), "r"(a[2]), "r"(a[3]), "r"(b[0]), "r"(b[1]));
}

#define SROW 20   // smem row stride in uints (= 40 bf16)

// ---------------- conv2 (implicit GEMM, bf16 split x3 MMA) ------------------
// M=1024 (co), K=11520, N=23104 (global px). Block 128x128xK32, 8 warps 64x32.
__global__ __launch_bounds__(256) void conv2_mma(const float* __restrict__ feat0)
{
    __shared__ unsigned Ash[128 * SROW], Asl[128 * SROW];
    __shared__ unsigned Bsh[128 * SROW], Bsl[128 * SROW];

    const int tid  = threadIdx.x;
    const int lane = tid & 31;
    const int w    = tid >> 5;
    const int gid  = lane >> 2, tig = lane & 3;
    const int wm   = w >> 2,    wn  = w & 3;          // 2 x 4 warp grid

    const int co0 = blockIdx.y * 128;
    const int n0  = blockIdx.x * 128;

    // ---- B gather state (fixed pixel per thread); race-free arithmetic offsets
    const int bpx  = tid >> 1;          // 0..127
    const int kq   = (tid & 1) * 16;    // 0 or 16
    const int pixg = n0 + bpx;
    const bool px_ok = (pixg < NPIX);
    int bimg = 0, sp0 = 0;
    unsigned vmask = 0;
    if (px_ok) {
        bimg = pixg / HW;
        int pix = pixg - bimg * HW;
        int oh = pix / H19, ow = pix - oh * H19;
        sp0 = pix;
        #pragma unroll
        for (int r = 0; r < 9; r++) {
            int ih = oh + r / 3 - 1, iw = ow + r % 3 - 1;
            if ((unsigned)ih < 19u && (unsigned)iw < 19u) vmask |= 1u << r;
        }
    }
    const float* catx_b = g_catx + (size_t)bimg * 256 * HW;
    const float* f0_b   = feat0  + (size_t)bimg * 1024 * HW;

    int cs = kq / 9, rs = kq - (kq / 9) * 9;   // incremental k -> (c, r)

    // ---- A load mapping ----
    const int arow  = tid >> 1;
    const int ahalf = tid & 1;
    const __nv_bfloat16* aph = g_w2h + (size_t)(co0 + arow) * C2K + ahalf * 16;
    const __nv_bfloat16* apl = g_w2l + (size_t)(co0 + arow) * C2K + ahalf * 16;

    float acc[4][4][4];
    #pragma unroll
    for (int mi = 0; mi < 4; mi++)
        #pragma unroll
        for (int ni = 0; ni < 4; ni++)
            #pragma unroll
            for (int e = 0; e < 4; e++) acc[mi][ni][e] = 0.f;

    for (int k0 = 0; k0 < C2K; k0 += 32) {
        // gather B (16 fp32 per thread)
        float fv[16];
        {
            int c = cs, r = rs;
            #pragma unroll
            for (int i = 0; i < 16; i++) {
                float v = 0.f;
                if (px_ok && ((vmask >> r) & 1u)) {
                    int dy  = (r * 11) >> 5;            // r/3 for r in [0,9)
                    int off = dy * H19 + (r - dy * 3) - 20;
                    const float* s = (c < 256) ? (catx_b + c * HW)
                                               : (f0_b + (c - 256) * HW);
                    v = s[sp0 + off];
                }
                fv[i] = v;
                if (++r == 9) { r = 0; ++c; }
            }
            cs += 3; rs += 5; if (rs >= 9) { rs -= 9; ++cs; }
        }
        uint4 ah0 = *(const uint4*)(aph + k0);
        uint4 ah1 = *(const uint4*)(aph + k0 + 8);
        uint4 al0 = *(const uint4*)(apl + k0);
        uint4 al1 = *(const uint4*)(apl + k0 + 8);

        __syncthreads();
        {
            unsigned* pa = Ash + arow * SROW + ahalf * 8;
            *(uint4*)pa = ah0; *(uint4*)(pa + 4) = ah1;
            unsigned* pl = Asl + arow * SROW + ahalf * 8;
            *(uint4*)pl = al0; *(uint4*)(pl + 4) = al1;
        }
        #pragma unroll
        for (int j = 0; j < 8; j++) {
            float x0 = fv[2 * j], x1 = fv[2 * j + 1];
            __nv_bfloat162 hh = __floats2bfloat162_rn(x0, x1);
            float r0 = x0 - __bfloat162float(hh.x);
            float r1 = x1 - __bfloat162float(hh.y);
            __nv_bfloat162 ll = __floats2bfloat162_rn(r0, r1);
            Bsh[bpx * SROW + kq / 2 + j] = *reinterpret_cast<unsigned*>(&hh);
            Bsl[bpx * SROW + kq / 2 + j] = *reinterpret_cast<unsigned*>(&ll);
        }
        __syncthreads();

        #pragma unroll
        for (int kk = 0; kk < 2; kk++) {
            const int koff = kk * 8;
            unsigned bh[4][2], bl[4][2];
            #pragma unroll
            for (int ni = 0; ni < 4; ni++) {
                int col = (wn * 32 + ni * 8 + gid) * SROW + koff + tig;
                bh[ni][0] = Bsh[col];     bh[ni][1] = Bsh[col + 4];
                bl[ni][0] = Bsl[col];     bl[ni][1] = Bsl[col + 4];
            }
            #pragma unroll
            for (int mi = 0; mi < 4; mi++) {
                int r0 = (wm * 64 + mi * 16 + gid) * SROW + koff + tig;
                int r1 = r0 + 8 * SROW;
                unsigned ah[4], al[4];
                ah[0] = Ash[r0]; ah[1] = Ash[r1]; ah[2] = Ash[r0 + 4]; ah[3] = Ash[r1 + 4];
                al[0] = Asl[r0]; al[1] = Asl[r1]; al[2] = Asl[r0 + 4]; al[3] = Asl[r1 + 4];
                #pragma unroll
                for (int ni = 0; ni < 4; ni++) {
                    mma16816(acc[mi][ni], ah, bh[ni]);
                    mma16816(acc[mi][ni], ah, bl[ni]);
                    mma16816(acc[mi][ni], al, bh[ni]);
                }
            }
        }
    }

    // epilogue: BN + leaky -> g_pre (documented c-fragment mapping)
    #pragma unroll
    for (int mi = 0; mi < 4; mi++) {
        int coA = co0 + wm * 64 + mi * 16 + gid;
        int coB = coA + 8;
        float sA = g_s2[coA], hA = g_h2[coA];
        float sB = g_s2[coB], hB = g_h2[coB];
        #pragma unroll
        for (int ni = 0; ni < 4; ni++) {
            int pg = n0 + wn * 32 + ni * 8 + 2 * tig;
            #pragma unroll
            for (int e = 0; e < 2; e++) {
                int p = pg + e;
                if (p < NPIX) {
                    int b = p / HW, pp = p - b * HW;
                    float y = acc[mi][ni][e] * sA + hA;
                    y = (y > 0.f) ? y : LEAK * y;
                    g_pre[((size_t)b * 1024 + coA) * HW + pp] = y;
                    float z = acc[mi][ni][2 + e] * sB + hB;
                    z = (z > 0.f) ? z : LEAK * z;
                    g_pre[((size_t)b * 1024 + coB) * HW + pp] = z;
                }
            }
        }
    }
}

// ---------------- det head GEMM (bf16 split x3 MMA) --------------------------
// M=600 (pad 640), K=1024, N=23104.
__global__ __launch_bounds__(256) void det_mma(float* __restrict__ out)
{
    __shared__ unsigned Ash[128 * SROW], Asl[128 * SROW];
    __shared__ unsigned Bsh[128 * SROW], Bsl[128 * SROW];

    const int tid  = threadIdx.x;
    const int lane = tid & 31;
    const int w    = tid >> 5;
    const int gid  = lane >> 2, tig = lane & 3;
    const int wm   = w >> 2,    wn  = w & 3;

    const int m0 = blockIdx.y * 128;
    const int n0 = blockIdx.x * 128;

    const int bpx  = tid >> 1;
    const int kq   = (tid & 1) * 16;
    const int pixg = n0 + bpx;
    const bool px_ok = (pixg < NPIX);
    int bimg = 0, pix = 0;
    if (px_ok) { bimg = pixg / HW; pix = pixg - bimg * HW; }
    const float* pb = g_pre + ((size_t)bimg * 1024 + kq) * HW + pix;

    const int arow  = tid >> 1;
    const int ahalf = tid & 1;
    const __nv_bfloat16* aph = g_rwh + (size_t)(m0 + arow) * 1024 + ahalf * 16;
    const __nv_bfloat16* apl = g_rwl + (size_t)(m0 + arow) * 1024 + ahalf * 16;

    float acc[4][4][4];
    #pragma unroll
    for (int mi = 0; mi < 4; mi++)
        #pragma unroll
        for (int ni = 0; ni < 4; ni++)
            #pragma unroll
            for (int e = 0; e < 4; e++) acc[mi][ni][e] = 0.f;

    for (int k0 = 0; k0 < 1024; k0 += 32) {
        float fv[16];
        #pragma unroll
        for (int i = 0; i < 16; i++)
            fv[i] = px_ok ? pb[(size_t)(k0 + i) * HW] : 0.f;

        uint4 ah0 = *(const uint4*)(aph + k0);
        uint4 ah1 = *(const uint4*)(aph + k0 + 8);
        uint4 al0 = *(const uint4*)(apl + k0);
        uint4 al1 = *(const uint4*)(apl + k0 + 8);

        __syncthreads();
        {
            unsigned* pa = Ash + arow * SROW + ahalf * 8;
            *(uint4*)pa = ah0; *(uint4*)(pa + 4) = ah1;
            unsigned* pl = Asl + arow * SROW + ahalf * 8;
            *(uint4*)pl = al0; *(uint4*)(pl + 4) = al1;
        }
        #pragma unroll
        for (int j = 0; j < 8; j++) {
            float x0 = fv[2 * j], x1 = fv[2 * j + 1];
            __nv_bfloat162 hh = __floats2bfloat162_rn(x0, x1);
            float r0 = x0 - __bfloat162float(hh.x);
            float r1 = x1 - __bfloat162float(hh.y);
            __nv_bfloat162 ll = __floats2bfloat162_rn(r0, r1);
            Bsh[bpx * SROW + kq / 2 + j] = *reinterpret_cast<unsigned*>(&hh);
            Bsl[bpx * SROW + kq / 2 + j] = *reinterpret_cast<unsigned*>(&ll);
        }
        __syncthreads();

        #pragma unroll
        for (int kk = 0; kk < 2; kk++) {
            const int koff = kk * 8;
            unsigned bh[4][2], bl[4][2];
            #pragma unroll
            for (int ni = 0; ni < 4; ni++) {
                int col = (wn * 32 + ni * 8 + gid) * SROW + koff + tig;
                bh[ni][0] = Bsh[col];     bh[ni][1] = Bsh[col + 4];
                bl[ni][0] = Bsl[col];     bl[ni][1] = Bsl[col + 4];
            }
            #pragma unroll
            for (int mi = 0; mi < 4; mi++) {
                int r0 = (wm * 64 + mi * 16 + gid) * SROW + koff + tig;
                int r1 = r0 + 8 * SROW;
                unsigned ah[4], al[4];
                ah[0] = Ash[r0]; ah[1] = Ash[r1]; ah[2] = Ash[r0 + 4]; ah[3] = Ash[r1 + 4];
                al[0] = Asl[r0]; al[1] = Asl[r1]; al[2] = Asl[r0 + 4]; al[3] = Asl[r1 + 4];
                #pragma unroll
                for (int ni = 0; ni < 4; ni++) {
                    mma16816(acc[mi][ni], ah, bh[ni]);
                    mma16816(acc[mi][ni], ah, bl[ni]);
                    mma16816(acc[mi][ni], al, bh[ni]);
                }
            }
        }
    }

    #pragma unroll
    for (int mi = 0; mi < 4; mi++) {
        int mA = m0 + wm * 64 + mi * 16 + gid;
        int mB = mA + 8;
        float cA = (mA < KO) ? g_cb[mA] : 0.f;
        float cB = (mB < KO) ? g_cb[mB] : 0.f;
        #pragma unroll
        for (int ni = 0; ni < 4; ni++) {
            int pg = n0 + wn * 32 + ni * 8 + 2 * tig;
            #pragma unroll
            for (int e = 0; e < 2; e++) {
                int p = pg + e;
                if (p < NPIX) {
                    int b = p / HW, pp = p - b * HW;
                    if (mA < KO)
                        out[((size_t)b * KO + mA) * HW + pp] = acc[mi][ni][e] + cA;
                    if (mB < KO)
                        out[((size_t)b * KO + mB) * HW + pp] = acc[mi][ni][2 + e] + cB;
                }
            }
        }
    }
}

// ---------------- launch ----------------------------------------------------
extern "C" void kernel_launch(void* const* d_in, const int* in_sizes, int n_in,
                              void* d_out, int out_size)
{
    const float* feat0 = (const float*)d_in[0];
    const float* feat1 = (const float*)d_in[1];
    const float* w1    = (const float*)d_in[2];
    const float* g1    = (const float*)d_in[3];
    const float* b1    = (const float*)d_in[4];
    const float* m1    = (const float*)d_in[5];
    const float* v1    = (const float*)d_in[6];
    const float* w2    = (const float*)d_in[7];
    const float* g2    = (const float*)d_in[8];
    const float* b2    = (const float*)d_in[9];
    const float* m2    = (const float*)d_in[10];
    const float* v2    = (const float*)d_in[11];
    const float* rw    = (const float*)d_in[12];
    float* out = (float*)d_out;

    prep_kernel<<<46080, 256>>>(w1, g1, b1, m1, v1, g2, b2, m2, v2, rw, w2);
    conv1_kernel<<<dim3(91, NB), 256>>>(feat1);
    conv2_mma<<<dim3(181, 8), 256>>>(feat0);   // N-tiles=ceil(23104/128), M-tiles=8
    det_mma  <<<dim3(181, 5), 256>>>(out);     // M-tiles=ceil(600/128)=5
}

// round 5
// speedup vs baseline: 2.2132x; 1.0833x over previous
#include <cuda_runtime.h>
#include <cuda_bf16.h>

#define LEAK  0.1f
#define BNEPS 1e-5f

#define NB    64
#define HW    361            // 19*19
#define H19   19
#define C2K   11520          // 1280*9
#define KO    600
#define KOP   640
#define NPIX  (NB * HW)      // 23104

#define SROW  20             // smem row stride in u32 (40 bf16)
#define AH    0
#define AL    2560
#define BH    5120
#define BL    7680
#define STG   10240          // u32 per stage
#define SMEMB (2 * STG * 4)  // 81920 bytes

// ---------------- device scratch ----------------
__device__ float g_w1t[512 * 64];
__device__ float g_s1[64],  g_h1[64];
__device__ float g_s2[1024], g_h2[1024];
__device__ float g_cb[KO];
__device__ unsigned g_xp  [(size_t)1280 * NPIX];   // conv2 input pairs [c][gpix]
__device__ unsigned g_prep[(size_t)1024 * NPIX];   // det   input pairs [c][gpix]
__device__ __align__(16) __nv_bfloat16 g_w2h[(size_t)1024 * C2K];
__device__ __align__(16) __nv_bfloat16 g_w2l[(size_t)1024 * C2K];
__device__ __align__(16) __nv_bfloat16 g_rwh[(size_t)KOP * 1024];
__device__ __align__(16) __nv_bfloat16 g_rwl[(size_t)KOP * 1024];

__device__ __forceinline__ unsigned packpair(float x)
{
    __nv_bfloat16 h = __float2bfloat16_rn(x);
    float r = x - __bfloat162float(h);
    __nv_bfloat16 l = __float2bfloat16_rn(r);
    return ((unsigned)*(unsigned short*)&l << 16) | *(unsigned short*)&h;
}

// ---------------- cp.async helpers ----------------
__device__ __forceinline__ void cp16(void* smem, const void* g)
{
    unsigned sa = (unsigned)__cvta_generic_to_shared(smem);
    asm volatile("cp.async.cg.shared.global [%0], [%1], 16;\n" :: "r"(sa), "l"(g));
}
__device__ __forceinline__ void cp_commit() { asm volatile("cp.async.commit_group;\n"); }
__device__ __forceinline__ void cp_wait0()  { asm volatile("cp.async.wait_group 0;\n"); }

// ---------------- prep: BN fold, transposes, bf16 hi/lo splits --------------
__global__ void prep_kernel(const float* __restrict__ w1,
                            const float* __restrict__ g1, const float* __restrict__ b1,
                            const float* __restrict__ m1, const float* __restrict__ v1,
                            const float* __restrict__ g2, const float* __restrict__ b2,
                            const float* __restrict__ m2, const float* __restrict__ v2,
                            const float* __restrict__ rw, const float* __restrict__ w2)
{
    long long i = (long long)blockIdx.x * blockDim.x + threadIdx.x;
    if (i < (long long)1024 * C2K) {
        float x = w2[i];
        __nv_bfloat16 h = __float2bfloat16_rn(x);
        g_w2h[i] = h;
        g_w2l[i] = __float2bfloat16_rn(x - __bfloat162float(h));
    }
    if (i < (long long)KOP * 1024) {
        int m = (int)(i >> 10), c = (int)(i & 1023);
        float x = (m < KO) ? rw[m * 1025 + c] : 0.f;
        __nv_bfloat16 h = __float2bfloat16_rn(x);
        g_rwh[i] = h;
        g_rwl[i] = __float2bfloat16_rn(x - __bfloat162float(h));
    }
    if (i < 512 * 64) {
        int k = (int)(i >> 6), co = (int)(i & 63);
        g_w1t[i] = w1[co * 512 + k];
    }
    if (i < KO)   g_cb[i] = rw[i * 1025 + 1024];
    if (i < 64)   { float s = g1[i] * rsqrtf(v1[i] + BNEPS); g_s1[i] = s; g_h1[i] = b1[i] - m1[i] * s; }
    if (i < 1024) { float s = g2[i] * rsqrtf(v2[i] + BNEPS); g_s2[i] = s; g_h2[i] = b2[i] - m2[i] * s; }
}

// ---------------- feat0 -> g_xp channels 256..1279 ----------------
__global__ void feat0_split(const float* __restrict__ feat0)
{
    long long i = (long long)blockIdx.x * blockDim.x + threadIdx.x;
    if (i < (long long)NB * 1024 * HW) {
        int hw = (int)(i % HW);
        long long t = i / HW;
        int c = (int)(t & 1023);
        int b = (int)(t >> 10);
        g_xp[(size_t)(256 + c) * NPIX + b * HW + hw] = packpair(feat0[i]);
    }
}

// ---------------- conv1 (1x1, 512->64) + BN + leaky + reorg(2) --------------
__global__ __launch_bounds__(256) void conv1_kernel(const float* __restrict__ feat1)
{
    __shared__ __align__(16) float s_in[512][16];
    __shared__ float s_w[64][64];

    const int b    = blockIdx.y;
    const int base = blockIdx.x * 16;
    const float* f = feat1 + (size_t)b * 512 * 1444;

    for (int idx = threadIdx.x; idx < 512 * 16; idx += 256) {
        int p = idx & 15, k = idx >> 4;
        int pix = base + p;
        s_in[k][p] = (pix < 1444) ? f[k * 1444 + pix] : 0.f;
    }

    const int co = threadIdx.x & 63;
    const int pq = threadIdx.x >> 6;
    float acc[4] = {0.f, 0.f, 0.f, 0.f};

    for (int kc = 0; kc < 512; kc += 64) {
        __syncthreads();
        for (int idx = threadIdx.x; idx < 64 * 64; idx += 256)
            s_w[idx >> 6][idx & 63] = g_w1t[(kc + (idx >> 6)) * 64 + (idx & 63)];
        __syncthreads();
        #pragma unroll
        for (int kk = 0; kk < 64; kk++) {
            float  w = s_w[kk][co];
            float4 v = *(const float4*)&s_in[kc + kk][pq * 4];
            acc[0] += v.x * w; acc[1] += v.y * w;
            acc[2] += v.z * w; acc[3] += v.w * w;
        }
    }

    const float s = g_s1[co], hh = g_h1[co];
    #pragma unroll
    for (int j = 0; j < 4; j++) {
        int pix = base + pq * 4 + j;
        if (pix < 1444) {
            float y = acc[j] * s + hh;
            y = (y > 0.f) ? y : LEAK * y;
            int h38 = pix / 38, w38 = pix - h38 * 38;
            int cc  = ((h38 & 1) * 2 + (w38 & 1)) * 64 + co;
            int gp  = b * HW + (h38 >> 1) * H19 + (w38 >> 1);
            g_xp[(size_t)cc * NPIX + gp] = packpair(y);
        }
    }
}

// ---------------- mma.sync helper (bf16, fp32 accum) ------------------------
__device__ __forceinline__ void mma16816(float* d, const unsigned* a, const unsigned* b)
{
    asm volatile(
        "mma.sync.aligned.m16n8k16.row.col.f32.bf16.bf16.f32 "
        "{%0,%1,%2,%3},{%4,%5,%6,%7},{%8,%9},{%0,%1,%2,%3};"
        : "+f"(d[0]), "+f"(d[1]), "+f"(d[2]), "+f"(d[3])
        : "r"(a[0]), "r"(a[1]), "r"(a[2]), "r"(a[3]), "r"(b[0]), "r"(b[1]));
}

// shared MMA consume step (same verified fragment mapping as R4)
__device__ __forceinline__ void mma_tile(const unsigned* Ah_, const unsigned* Al_,
                                         const unsigned* Bh_, const unsigned* Bl_,
                                         int wm, int wn, int gid, int tig,
                                         float acc[4][4][4])
{
    #pragma unroll
    for (int kk = 0; kk < 2; kk++) {
        const int koff = kk * 8;
        unsigned bh[4][2], bl[4][2];
        #pragma unroll
        for (int ni = 0; ni < 4; ni++) {
            int col = (wn * 32 + ni * 8 + gid) * SROW + koff + tig;
            bh[ni][0] = Bh_[col]; bh[ni][1] = Bh_[col + 4];
            bl[ni][0] = Bl_[col]; bl[ni][1] = Bl_[col + 4];
        }
        #pragma unroll
        for (int mi = 0; mi < 4; mi++) {
            int r0 = (wm * 64 + mi * 16 + gid) * SROW + koff + tig;
            int r1 = r0 + 8 * SROW;
            unsigned ah[4], al[4];
            ah[0] = Ah_[r0]; ah[1] = Ah_[r1]; ah[2] = Ah_[r0 + 4]; ah[3] = Ah_[r1 + 4];
            al[0] = Al_[r0]; al[1] = Al_[r1]; al[2] = Al_[r0 + 4]; al[3] = Al_[r1 + 4];
            #pragma unroll
            for (int ni = 0; ni < 4; ni++) {
                mma16816(acc[mi][ni], ah, bh[ni]);
                mma16816(acc[mi][ni], ah, bl[ni]);
                mma16816(acc[mi][ni], al, bh[ni]);
            }
        }
    }
}

// ---------------- conv2 (implicit GEMM, pipelined) ---------------------------
// M=1024(co) x K=11520 x N=23104. Block 128x128xK32, 8 warps 64x32.
__global__ __launch_bounds__(256) void conv2_mma()
{
    extern __shared__ unsigned sm[];

    const int tid  = threadIdx.x;
    const int lane = tid & 31;
    const int w    = tid >> 5;
    const int gid  = lane >> 2, tig = lane & 3;
    const int wm   = w >> 2,    wn  = w & 3;

    const int co0 = blockIdx.y * 128;
    const int n0  = blockIdx.x * 128;

    // ---- B gather state ----
    const int bpx  = tid >> 1;
    const int kq   = (tid & 1) * 16;
    const int pixg = n0 + bpx;
    const bool px_ok = (pixg < NPIX);
    int sp_base = 0;
    unsigned vmask = 0;
    if (px_ok) {
        int bimg = pixg / HW;
        int pix  = pixg - bimg * HW;
        int oh = pix / H19, ow = pix - oh * H19;
        sp_base = bimg * HW + pix;
        #pragma unroll
        for (int r = 0; r < 9; r++) {
            int ih = oh + r / 3 - 1, iw = ow + r % 3 - 1;
            if ((unsigned)ih < 19u && (unsigned)iw < 19u) vmask |= 1u << r;
        }
    }
    int cs = kq / 9, rs = kq - (kq / 9) * 9;

    // ---- A cp.async mapping ----
    const int arow  = tid >> 1;
    const int ahalf = tid & 1;
    const __nv_bfloat16* aph = g_w2h + (size_t)(co0 + arow) * C2K + ahalf * 16;
    const __nv_bfloat16* apl = g_w2l + (size_t)(co0 + arow) * C2K + ahalf * 16;
    const int adst = arow * SROW + ahalf * 8;   // u32 offset in stage

    float acc[4][4][4];
    #pragma unroll
    for (int mi = 0; mi < 4; mi++)
        #pragma unroll
        for (int ni = 0; ni < 4; ni++)
            #pragma unroll
            for (int e = 0; e < 4; e++) acc[mi][ni][e] = 0.f;

    unsigned fv[16];

    // gather B for iteration `it` range [kq, kq+16)
    auto gatherB = [&](unsigned* dst) {
        int c = cs, r = rs;
        #pragma unroll
        for (int i = 0; i < 16; i++) {
            unsigned v = 0u;
            if (px_ok && ((vmask >> r) & 1u)) {
                int dy  = (r * 11) >> 5;
                int off = dy * H19 + (r - dy * 3) - 20;
                v = g_xp[(size_t)c * NPIX + sp_base + off];
            }
            dst[i] = v;
            if (++r == 9) { r = 0; ++c; }
        }
        cs += 3; rs += 5; if (rs >= 9) { rs -= 9; ++cs; }
    };

    // prologue: A(0) via cp.async, B(0) into regs
    cp16(sm + AH + adst,     aph);
    cp16(sm + AH + adst + 4, aph + 8);
    cp16(sm + AL + adst,     apl);
    cp16(sm + AL + adst + 4, apl + 8);
    cp_commit();
    gatherB(fv);

    const int NIT = C2K / 32;   // 360
    int s = 0;
    for (int it = 0; it < NIT; it++) {
        unsigned* base = sm + s * STG;
        // store B regs -> stage s
        {
            unsigned* bh = base + BH + bpx * SROW + (kq >> 1);
            unsigned* bl = base + BL + bpx * SROW + (kq >> 1);
            #pragma unroll
            for (int j = 0; j < 8; j++) {
                bh[j] = __byte_perm(fv[2 * j], fv[2 * j + 1], 0x5410);
                bl[j] = __byte_perm(fv[2 * j], fv[2 * j + 1], 0x7632);
            }
        }
        cp_wait0();
        __syncthreads();

        if (it + 1 < NIT) {
            unsigned* nbase = sm + (s ^ 1) * STG;
            const __nv_bfloat16* ph = aph + (it + 1) * 32;
            const __nv_bfloat16* pl = apl + (it + 1) * 32;
            cp16(nbase + AH + adst,     ph);
            cp16(nbase + AH + adst + 4, ph + 8);
            cp16(nbase + AL + adst,     pl);
            cp16(nbase + AL + adst + 4, pl + 8);
            cp_commit();
            gatherB(fv);    // overlaps MMAs below
        }

        mma_tile(base + AH, base + AL, base + BH, base + BL,
                 wm, wn, gid, tig, acc);
        s ^= 1;
    }

    // epilogue: BN + leaky -> g_prep pairs [co][gpix]
    #pragma unroll
    for (int mi = 0; mi < 4; mi++) {
        int coA = co0 + wm * 64 + mi * 16 + gid;
        int coB = coA + 8;
        float sA = g_s2[coA], hA = g_h2[coA];
        float sB = g_s2[coB], hB = g_h2[coB];
        #pragma unroll
        for (int ni = 0; ni < 4; ni++) {
            int pg = n0 + wn * 32 + ni * 8 + 2 * tig;
            #pragma unroll
            for (int e = 0; e < 2; e++) {
                int p = pg + e;
                if (p < NPIX) {
                    float y = acc[mi][ni][e] * sA + hA;
                    y = (y > 0.f) ? y : LEAK * y;
                    g_prep[(size_t)coA * NPIX + p] = packpair(y);
                    float z = acc[mi][ni][2 + e] * sB + hB;
                    z = (z > 0.f) ? z : LEAK * z;
                    g_prep[(size_t)coB * NPIX + p] = packpair(z);
                }
            }
        }
    }
}

// ---------------- det head GEMM (pipelined) ----------------------------------
// M=640(pad) x K=1024 x N=23104.
__global__ __launch_bounds__(256) void det_mma(float* __restrict__ out)
{
    extern __shared__ unsigned sm[];

    const int tid  = threadIdx.x;
    const int lane = tid & 31;
    const int w    = tid >> 5;
    const int gid  = lane >> 2, tig = lane & 3;
    const int wm   = w >> 2,    wn  = w & 3;

    const int m0 = blockIdx.y * 128;
    const int n0 = blockIdx.x * 128;

    const int bpx  = tid >> 1;
    const int kq   = (tid & 1) * 16;
    const int pixg = n0 + bpx;
    const bool px_ok = (pixg < NPIX);
    const unsigned* pb = g_prep + (size_t)kq * NPIX + (px_ok ? pixg : 0);

    const int arow  = tid >> 1;
    const int ahalf = tid & 1;
    const __nv_bfloat16* aph = g_rwh + (size_t)(m0 + arow) * 1024 + ahalf * 16;
    const __nv_bfloat16* apl = g_rwl + (size_t)(m0 + arow) * 1024 + ahalf * 16;
    const int adst = arow * SROW + ahalf * 8;

    float acc[4][4][4];
    #pragma unroll
    for (int mi = 0; mi < 4; mi++)
        #pragma unroll
        for (int ni = 0; ni < 4; ni++)
            #pragma unroll
            for (int e = 0; e < 4; e++) acc[mi][ni][e] = 0.f;

    unsigned fv[16];
    auto gatherB = [&](unsigned* dst, int k0) {
        #pragma unroll
        for (int i = 0; i < 16; i++)
            dst[i] = px_ok ? pb[(size_t)(k0 + i) * NPIX] : 0u;
    };

    cp16(sm + AH + adst,     aph);
    cp16(sm + AH + adst + 4, aph + 8);
    cp16(sm + AL + adst,     apl);
    cp16(sm + AL + adst + 4, apl + 8);
    cp_commit();
    gatherB(fv, 0);

    const int NIT = 1024 / 32;   // 32
    int s = 0;
    for (int it = 0; it < NIT; it++) {
        unsigned* base = sm + s * STG;
        {
            unsigned* bh = base + BH + bpx * SROW + (kq >> 1);
            unsigned* bl = base + BL + bpx * SROW + (kq >> 1);
            #pragma unroll
            for (int j = 0; j < 8; j++) {
                bh[j] = __byte_perm(fv[2 * j], fv[2 * j + 1], 0x5410);
                bl[j] = __byte_perm(fv[2 * j], fv[2 * j + 1], 0x7632);
            }
        }
        cp_wait0();
        __syncthreads();

        if (it + 1 < NIT) {
            unsigned* nbase = sm + (s ^ 1) * STG;
            const __nv_bfloat16* ph = aph + (it + 1) * 32;
            const __nv_bfloat16* pl = apl + (it + 1) * 32;
            cp16(nbase + AH + adst,     ph);
            cp16(nbase + AH + adst + 4, ph + 8);
            cp16(nbase + AL + adst,     pl);
            cp16(nbase + AL + adst + 4, pl + 8);
            cp_commit();
            gatherB(fv, (it + 1) * 32);
        }

        mma_tile(base + AH, base + AL, base + BH, base + BL,
                 wm, wn, gid, tig, acc);
        s ^= 1;
    }

    #pragma unroll
    for (int mi = 0; mi < 4; mi++) {
        int mA = m0 + wm * 64 + mi * 16 + gid;
        int mB = mA + 8;
        float cA = (mA < KO) ? g_cb[mA] : 0.f;
        float cB = (mB < KO) ? g_cb[mB] : 0.f;
        #pragma unroll
        for (int ni = 0; ni < 4; ni++) {
            int pg = n0 + wn * 32 + ni * 8 + 2 * tig;
            #pragma unroll
            for (int e = 0; e < 2; e++) {
                int p = pg + e;
                if (p < NPIX) {
                    int b = p / HW, pp = p - b * HW;
                    if (mA < KO)
                        out[((size_t)b * KO + mA) * HW + pp] = acc[mi][ni][e] + cA;
                    if (mB < KO)
                        out[((size_t)b * KO + mB) * HW + pp] = acc[mi][ni][2 + e] + cB;
                }
            }
        }
    }
}

// ---------------- launch ----------------------------------------------------
extern "C" void kernel_launch(void* const* d_in, const int* in_sizes, int n_in,
                              void* d_out, int out_size)
{
    const float* feat0 = (const float*)d_in[0];
    const float* feat1 = (const float*)d_in[1];
    const float* w1    = (const float*)d_in[2];
    const float* g1    = (const float*)d_in[3];
    const float* b1    = (const float*)d_in[4];
    const float* m1    = (const float*)d_in[5];
    const float* v1    = (const float*)d_in[6];
    const float* w2    = (const float*)d_in[7];
    const float* g2    = (const float*)d_in[8];
    const float* b2    = (const float*)d_in[9];
    const float* m2    = (const float*)d_in[10];
    const float* v2    = (const float*)d_in[11];
    const float* rw    = (const float*)d_in[12];
    float* out = (float*)d_out;

    cudaFuncSetAttribute(conv2_mma, cudaFuncAttributeMaxDynamicSharedMemorySize, SMEMB);
    cudaFuncSetAttribute(det_mma,   cudaFuncAttributeMaxDynamicSharedMemorySize, SMEMB);

    prep_kernel<<<46080, 256>>>(w1, g1, b1, m1, v1, g2, b2, m2, v2, rw, w2);
    feat0_split<<<92416, 256>>>(feat0);
    conv1_kernel<<<dim3(91, NB), 256>>>(feat1);
    conv2_mma<<<dim3(181, 8), 256, SMEMB>>>();
    det_mma  <<<dim3(181, 5), 256, SMEMB>>>(out);
}

// round 6
// speedup vs baseline: 2.7687x; 1.2510x over previous
#include <cuda_runtime.h>
#include <cuda_bf16.h>

#define LEAK  0.1f
#define BNEPS 1e-5f

#define NB    64
#define HW    361            // 19*19
#define H19   19
#define C2IN  1280
#define C2K   11520          // 1280*9
#define KO    600
#define KOP   640
#define NPIX  (NB * HW)      // 23104

#define SROW  20             // smem row stride in u32 (40 bf16)
#define AH    0
#define AL    2560
#define BH    5120
#define BL    7680
#define STG   10240          // u32 per stage
#define SMEMB (2 * STG * 4)  // 81920 bytes

// ---------------- device scratch ----------------
__device__ float g_w1t[512 * 64];
__device__ float g_s1[64],  g_h1[64];
__device__ float g_s2[1024], g_h2[1024];
__device__ float g_cb[KO];
__device__ unsigned g_xp  [(size_t)C2IN * NPIX];   // conv2 input pairs [c][gpix]
__device__ unsigned g_prep[(size_t)1024 * NPIX];   // det   input pairs [c][gpix]
__device__ __align__(16) __nv_bfloat16 g_w2h[(size_t)1024 * C2K];  // K-order r*1280+c
__device__ __align__(16) __nv_bfloat16 g_w2l[(size_t)1024 * C2K];
__device__ __align__(16) __nv_bfloat16 g_rwh[(size_t)KOP * 1024];
__device__ __align__(16) __nv_bfloat16 g_rwl[(size_t)KOP * 1024];

__device__ __forceinline__ unsigned packpair(float x)
{
    __nv_bfloat16 h = __float2bfloat16_rn(x);
    float r = x - __bfloat162float(h);
    __nv_bfloat16 l = __float2bfloat16_rn(r);
    return ((unsigned)*(unsigned short*)&l << 16) | *(unsigned short*)&h;
}

// ---------------- cp.async helpers ----------------
__device__ __forceinline__ void cp16(void* smem, const void* g)
{
    unsigned sa = (unsigned)__cvta_generic_to_shared(smem);
    asm volatile("cp.async.cg.shared.global [%0], [%1], 16;\n" :: "r"(sa), "l"(g));
}
__device__ __forceinline__ void cp_commit() { asm volatile("cp.async.commit_group;\n"); }
__device__ __forceinline__ void cp_wait0()  { asm volatile("cp.async.wait_group 0;\n"); }

// ---------------- prep: BN fold, transposes, bf16 hi/lo splits --------------
// w2 split is emitted in permuted K-order k' = r*1280 + c (c fastest).
__global__ void prep_kernel(const float* __restrict__ w1,
                            const float* __restrict__ g1, const float* __restrict__ b1,
                            const float* __restrict__ m1, const float* __restrict__ v1,
                            const float* __restrict__ g2, const float* __restrict__ b2,
                            const float* __restrict__ m2, const float* __restrict__ v2,
                            const float* __restrict__ rw, const float* __restrict__ w2)
{
    long long i = (long long)blockIdx.x * blockDim.x + threadIdx.x;
    if (i < (long long)1024 * C2K) {
        // destination-indexed: i = co*C2K + r*1280 + c  -> src co*C2K + c*9 + r
        int co = (int)(i / C2K);
        int t  = (int)(i - (long long)co * C2K);
        int r  = t / C2IN;
        int c  = t - r * C2IN;
        float x = w2[(size_t)co * C2K + c * 9 + r];
        __nv_bfloat16 h = __float2bfloat16_rn(x);
        g_w2h[i] = h;
        g_w2l[i] = __float2bfloat16_rn(x - __bfloat162float(h));
    }
    if (i < (long long)KOP * 1024) {
        int m = (int)(i >> 10), c = (int)(i & 1023);
        float x = (m < KO) ? rw[m * 1025 + c] : 0.f;
        __nv_bfloat16 h = __float2bfloat16_rn(x);
        g_rwh[i] = h;
        g_rwl[i] = __float2bfloat16_rn(x - __bfloat162float(h));
    }
    if (i < 512 * 64) {
        int k = (int)(i >> 6), co = (int)(i & 63);
        g_w1t[i] = w1[co * 512 + k];
    }
    if (i < KO)   g_cb[i] = rw[i * 1025 + 1024];
    if (i < 64)   { float s = g1[i] * rsqrtf(v1[i] + BNEPS); g_s1[i] = s; g_h1[i] = b1[i] - m1[i] * s; }
    if (i < 1024) { float s = g2[i] * rsqrtf(v2[i] + BNEPS); g_s2[i] = s; g_h2[i] = b2[i] - m2[i] * s; }
}

// ---------------- feat0 -> g_xp channels 256..1279 ----------------
__global__ void feat0_split(const float* __restrict__ feat0)
{
    long long i = (long long)blockIdx.x * blockDim.x + threadIdx.x;
    if (i < (long long)NB * 1024 * HW) {
        int hw = (int)(i % HW);
        long long t = i / HW;
        int c = (int)(t & 1023);
        int b = (int)(t >> 10);
        g_xp[(size_t)(256 + c) * NPIX + b * HW + hw] = packpair(feat0[i]);
    }
}

// ---------------- conv1 (1x1, 512->64) + BN + leaky + reorg(2) --------------
__global__ __launch_bounds__(256) void conv1_kernel(const float* __restrict__ feat1)
{
    __shared__ __align__(16) float s_in[512][16];
    __shared__ float s_w[64][64];

    const int b    = blockIdx.y;
    const int base = blockIdx.x * 16;
    const float* f = feat1 + (size_t)b * 512 * 1444;

    for (int idx = threadIdx.x; idx < 512 * 16; idx += 256) {
        int p = idx & 15, k = idx >> 4;
        int pix = base + p;
        s_in[k][p] = (pix < 1444) ? f[k * 1444 + pix] : 0.f;
    }

    const int co = threadIdx.x & 63;
    const int pq = threadIdx.x >> 6;
    float acc[4] = {0.f, 0.f, 0.f, 0.f};

    for (int kc = 0; kc < 512; kc += 64) {
        __syncthreads();
        for (int idx = threadIdx.x; idx < 64 * 64; idx += 256)
            s_w[idx >> 6][idx & 63] = g_w1t[(kc + (idx >> 6)) * 64 + (idx & 63)];
        __syncthreads();
        #pragma unroll
        for (int kk = 0; kk < 64; kk++) {
            float  w = s_w[kk][co];
            float4 v = *(const float4*)&s_in[kc + kk][pq * 4];
            acc[0] += v.x * w; acc[1] += v.y * w;
            acc[2] += v.z * w; acc[3] += v.w * w;
        }
    }

    const float s = g_s1[co], hh = g_h1[co];
    #pragma unroll
    for (int j = 0; j < 4; j++) {
        int pix = base + pq * 4 + j;
        if (pix < 1444) {
            float y = acc[j] * s + hh;
            y = (y > 0.f) ? y : LEAK * y;
            int h38 = pix / 38, w38 = pix - h38 * 38;
            int cc  = ((h38 & 1) * 2 + (w38 & 1)) * 64 + co;
            int gp  = b * HW + (h38 >> 1) * H19 + (w38 >> 1);
            g_xp[(size_t)cc * NPIX + gp] = packpair(y);
        }
    }
}

// ---------------- mma.sync helper (bf16, fp32 accum) ------------------------
__device__ __forceinline__ void mma16816(float* d, const unsigned* a, const unsigned* b)
{
    asm volatile(
        "mma.sync.aligned.m16n8k16.row.col.f32.bf16.bf16.f32 "
        "{%0,%1,%2,%3},{%4,%5,%6,%7},{%8,%9},{%0,%1,%2,%3};"
        : "+f"(d[0]), "+f"(d[1]), "+f"(d[2]), "+f"(d[3])
        : "r"(a[0]), "r"(a[1]), "r"(a[2]), "r"(a[3]), "r"(b[0]), "r"(b[1]));
}

__device__ __forceinline__ void mma_tile(const unsigned* Ah_, const unsigned* Al_,
                                         const unsigned* Bh_, const unsigned* Bl_,
                                         int wm, int wn, int gid, int tig,
                                         float acc[4][4][4])
{
    #pragma unroll
    for (int kk = 0; kk < 2; kk++) {
        const int koff = kk * 8;
        unsigned bh[4][2], bl[4][2];
        #pragma unroll
        for (int ni = 0; ni < 4; ni++) {
            int col = (wn * 32 + ni * 8 + gid) * SROW + koff + tig;
            bh[ni][0] = Bh_[col]; bh[ni][1] = Bh_[col + 4];
            bl[ni][0] = Bl_[col]; bl[ni][1] = Bl_[col + 4];
        }
        #pragma unroll
        for (int mi = 0; mi < 4; mi++) {
            int r0 = (wm * 64 + mi * 16 + gid) * SROW + koff + tig;
            int r1 = r0 + 8 * SROW;
            unsigned ah[4], al[4];
            ah[0] = Ah_[r0]; ah[1] = Ah_[r1]; ah[2] = Ah_[r0 + 4]; ah[3] = Ah_[r1 + 4];
            al[0] = Al_[r0]; al[1] = Al_[r1]; al[2] = Al_[r0 + 4]; al[3] = Al_[r1 + 4];
            #pragma unroll
            for (int ni = 0; ni < 4; ni++) {
                mma16816(acc[mi][ni], ah, bh[ni]);
                mma16816(acc[mi][ni], ah, bl[ni]);
                mma16816(acc[mi][ni], al, bh[ni]);
            }
        }
    }
}

// ---------------- conv2 (implicit GEMM, pipelined, K-order r-major) ---------
__global__ __launch_bounds__(256, 2) void conv2_mma()
{
    extern __shared__ unsigned sm[];

    const int tid  = threadIdx.x;
    const int lane = tid & 31;
    const int w    = tid >> 5;
    const int gid  = lane >> 2, tig = lane & 3;
    const int wm   = w >> 2,    wn  = w & 3;

    const int co0 = blockIdx.y * 128;
    const int n0  = blockIdx.x * 128;

    // ---- B gather state ----
    const int bpx  = tid >> 1;
    const int kq   = (tid & 1) * 16;
    const int pixg = n0 + bpx;
    const bool px_ok = (pixg < NPIX);
    int sp_base = 0;
    unsigned vmask = 0;
    if (px_ok) {
        int bimg = pixg / HW;
        int pix  = pixg - bimg * HW;
        int oh = pix / H19, ow = pix - oh * H19;
        sp_base = bimg * HW + pix;
        #pragma unroll
        for (int r = 0; r < 9; r++) {
            int ih = oh + r / 3 - 1, iw = ow + r % 3 - 1;
            if ((unsigned)ih < 19u && (unsigned)iw < 19u) vmask |= 1u << r;
        }
    }
    // K-order: k' = r*1280 + c. Thread covers [it*32+kq, it*32+kq+16): fixed r,
    // 16 consecutive channels (alignment: kq,c multiples of 16, 1280%32==0).
    int cB = kq, rB = 0;

    // ---- A cp.async mapping ----
    const int arow  = tid >> 1;
    const int ahalf = tid & 1;
    const __nv_bfloat16* aph = g_w2h + (size_t)(co0 + arow) * C2K + ahalf * 16;
    const __nv_bfloat16* apl = g_w2l + (size_t)(co0 + arow) * C2K + ahalf * 16;
    const int adst = arow * SROW + ahalf * 8;

    float acc[4][4][4];
    #pragma unroll
    for (int mi = 0; mi < 4; mi++)
        #pragma unroll
        for (int ni = 0; ni < 4; ni++)
            #pragma unroll
            for (int e = 0; e < 4; e++) acc[mi][ni][e] = 0.f;

    unsigned fv[16];
    auto gatherB = [&](unsigned* dst) {
        bool val = px_ok && ((vmask >> rB) & 1u);
        int dy  = (rB * 11) >> 5;
        int off = dy * H19 + (rB - dy * 3) - 20;
        const unsigned* p = g_xp + (size_t)cB * NPIX + (sp_base + off);
        #pragma unroll
        for (int i = 0; i < 16; i++)
            dst[i] = val ? p[(size_t)i * NPIX] : 0u;
        cB += 32;
        if (cB >= C2IN) { cB -= C2IN; ++rB; }
    };

    cp16(sm + AH + adst,     aph);
    cp16(sm + AH + adst + 4, aph + 8);
    cp16(sm + AL + adst,     apl);
    cp16(sm + AL + adst + 4, apl + 8);
    cp_commit();
    gatherB(fv);

    const int NIT = C2K / 32;   // 360
    int s = 0;
    for (int it = 0; it < NIT; it++) {
        unsigned* base = sm + s * STG;
        {
            unsigned* bh = base + BH + bpx * SROW + (kq >> 1);
            unsigned* bl = base + BL + bpx * SROW + (kq >> 1);
            #pragma unroll
            for (int j = 0; j < 8; j++) {
                bh[j] = __byte_perm(fv[2 * j], fv[2 * j + 1], 0x5410);
                bl[j] = __byte_perm(fv[2 * j], fv[2 * j + 1], 0x7632);
            }
        }
        cp_wait0();
        __syncthreads();

        if (it + 1 < NIT) {
            unsigned* nbase = sm + (s ^ 1) * STG;
            const __nv_bfloat16* ph = aph + (it + 1) * 32;
            const __nv_bfloat16* pl = apl + (it + 1) * 32;
            cp16(nbase + AH + adst,     ph);
            cp16(nbase + AH + adst + 4, ph + 8);
            cp16(nbase + AL + adst,     pl);
            cp16(nbase + AL + adst + 4, pl + 8);
            cp_commit();
            gatherB(fv);
        }

        mma_tile(base + AH, base + AL, base + BH, base + BL,
                 wm, wn, gid, tig, acc);
        s ^= 1;
    }

    // epilogue: BN + leaky -> g_prep pairs [co][gpix]
    #pragma unroll
    for (int mi = 0; mi < 4; mi++) {
        int coA = co0 + wm * 64 + mi * 16 + gid;
        int coB = coA + 8;
        float sA = g_s2[coA], hA = g_h2[coA];
        float sB = g_s2[coB], hB = g_h2[coB];
        #pragma unroll
        for (int ni = 0; ni < 4; ni++) {
            int pg = n0 + wn * 32 + ni * 8 + 2 * tig;
            #pragma unroll
            for (int e = 0; e < 2; e++) {
                int p = pg + e;
                if (p < NPIX) {
                    float y = acc[mi][ni][e] * sA + hA;
                    y = (y > 0.f) ? y : LEAK * y;
                    g_prep[(size_t)coA * NPIX + p] = packpair(y);
                    float z = acc[mi][ni][2 + e] * sB + hB;
                    z = (z > 0.f) ? z : LEAK * z;
                    g_prep[(size_t)coB * NPIX + p] = packpair(z);
                }
            }
        }
    }
}

// ---------------- det head GEMM (pipelined) ----------------------------------
__global__ __launch_bounds__(256, 2) void det_mma(float* __restrict__ out)
{
    extern __shared__ unsigned sm[];

    const int tid  = threadIdx.x;
    const int lane = tid & 31;
    const int w    = tid >> 5;
    const int gid  = lane >> 2, tig = lane & 3;
    const int wm   = w >> 2,    wn  = w & 3;

    const int m0 = blockIdx.y * 128;
    const int n0 = blockIdx.x * 128;

    const int bpx  = tid >> 1;
    const int kq   = (tid & 1) * 16;
    const int pixg = n0 + bpx;
    const bool px_ok = (pixg < NPIX);
    const unsigned* pb = g_prep + (size_t)kq * NPIX + (px_ok ? pixg : 0);

    const int arow  = tid >> 1;
    const int ahalf = tid & 1;
    const __nv_bfloat16* aph = g_rwh + (size_t)(m0 + arow) * 1024 + ahalf * 16;
    const __nv_bfloat16* apl = g_rwl + (size_t)(m0 + arow) * 1024 + ahalf * 16;
    const int adst = arow * SROW + ahalf * 8;

    float acc[4][4][4];
    #pragma unroll
    for (int mi = 0; mi < 4; mi++)
        #pragma unroll
        for (int ni = 0; ni < 4; ni++)
            #pragma unroll
            for (int e = 0; e < 4; e++) acc[mi][ni][e] = 0.f;

    unsigned fv[16];
    auto gatherB = [&](unsigned* dst, int k0) {
        const unsigned* p = pb + (size_t)k0 * NPIX;
        #pragma unroll
        for (int i = 0; i < 16; i++)
            dst[i] = px_ok ? p[(size_t)i * NPIX] : 0u;
    };

    cp16(sm + AH + adst,     aph);
    cp16(sm + AH + adst + 4, aph + 8);
    cp16(sm + AL + adst,     apl);
    cp16(sm + AL + adst + 4, apl + 8);
    cp_commit();
    gatherB(fv, 0);

    const int NIT = 1024 / 32;
    int s = 0;
    for (int it = 0; it < NIT; it++) {
        unsigned* base = sm + s * STG;
        {
            unsigned* bh = base + BH + bpx * SROW + (kq >> 1);
            unsigned* bl = base + BL + bpx * SROW + (kq >> 1);
            #pragma unroll
            for (int j = 0; j < 8; j++) {
                bh[j] = __byte_perm(fv[2 * j], fv[2 * j + 1], 0x5410);
                bl[j] = __byte_perm(fv[2 * j], fv[2 * j + 1], 0x7632);
            }
        }
        cp_wait0();
        __syncthreads();

        if (it + 1 < NIT) {
            unsigned* nbase = sm + (s ^ 1) * STG;
            const __nv_bfloat16* ph = aph + (it + 1) * 32;
            const __nv_bfloat16* pl = apl + (it + 1) * 32;
            cp16(nbase + AH + adst,     ph);
            cp16(nbase + AH + adst + 4, ph + 8);
            cp16(nbase + AL + adst,     pl);
            cp16(nbase + AL + adst + 4, pl + 8);
            cp_commit();
            gatherB(fv, (it + 1) * 32);
        }

        mma_tile(base + AH, base + AL, base + BH, base + BL,
                 wm, wn, gid, tig, acc);
        s ^= 1;
    }

    #pragma unroll
    for (int mi = 0; mi < 4; mi++) {
        int mA = m0 + wm * 64 + mi * 16 + gid;
        int mB = mA + 8;
        float cA = (mA < KO) ? g_cb[mA] : 0.f;
        float cB = (mB < KO) ? g_cb[mB] : 0.f;
        #pragma unroll
        for (int ni = 0; ni < 4; ni++) {
            int pg = n0 + wn * 32 + ni * 8 + 2 * tig;
            #pragma unroll
            for (int e = 0; e < 2; e++) {
                int p = pg + e;
                if (p < NPIX) {
                    int b = p / HW, pp = p - b * HW;
                    if (mA < KO)
                        out[((size_t)b * KO + mA) * HW + pp] = acc[mi][ni][e] + cA;
                    if (mB < KO)
                        out[((size_t)b * KO + mB) * HW + pp] = acc[mi][ni][2 + e] + cB;
                }
            }
        }
    }
}

// ---------------- launch ----------------------------------------------------
extern "C" void kernel_launch(void* const* d_in, const int* in_sizes, int n_in,
                              void* d_out, int out_size)
{
    const float* feat0 = (const float*)d_in[0];
    const float* feat1 = (const float*)d_in[1];
    const float* w1    = (const float*)d_in[2];
    const float* g1    = (const float*)d_in[3];
    const float* b1    = (const float*)d_in[4];
    const float* m1    = (const float*)d_in[5];
    const float* v1    = (const float*)d_in[6];
    const float* w2    = (const float*)d_in[7];
    const float* g2    = (const float*)d_in[8];
    const float* b2    = (const float*)d_in[9];
    const float* m2    = (const float*)d_in[10];
    const float* v2    = (const float*)d_in[11];
    const float* rw    = (const float*)d_in[12];
    float* out = (float*)d_out;

    cudaFuncSetAttribute(conv2_mma, cudaFuncAttributeMaxDynamicSharedMemorySize, SMEMB);
    cudaFuncSetAttribute(det_mma,   cudaFuncAttributeMaxDynamicSharedMemorySize, SMEMB);

    prep_kernel<<<46080, 256>>>(w1, g1, b1, m1, v1, g2, b2, m2, v2, rw, w2);
    feat0_split<<<92416, 256>>>(feat0);
    conv1_kernel<<<dim3(91, NB), 256>>>(feat1);
    conv2_mma<<<dim3(181, 8), 256, SMEMB>>>();
    det_mma  <<<dim3(181, 5), 256, SMEMB>>>(out);
}

// round 8
// speedup vs baseline: 3.1810x; 1.1489x over previous
#include <cuda_runtime.h>
#include <cuda_fp16.h>

#define LEAK  0.1f
#define BNEPS 1e-5f

#define NB    64
#define HW    361            // 19*19
#define H19   19
#define C2IN  1280
#define C2K   11520          // 1280*9
#define KO    600
#define KOP   640
#define NPIX  (NB * HW)      // 23104

#define SROW  20             // smem row stride in u32
#define AH0   0              // k' chunk 0 (orig k 0..15 of iter)
#define AH1   2560           // k' chunk 1 (orig k 16..31)
#define BH0   5120
#define BH1   7680
#define STG   10240          // u32 per stage
#define SMEMB (2 * STG * 4)  // 81920 bytes

// ---------------- device scratch ----------------
__device__ float g_w1t[512 * 64];
__device__ float g_s1[64],  g_h1[64];
__device__ float g_s2[1024], g_h2[1024];
__device__ float g_cb[KO];
__device__ unsigned g_xp  [(size_t)C2IN * NPIX];   // conv2 input (h,l) fp16 pairs [c][gpix]
__device__ unsigned g_prep[(size_t)1024 * NPIX];   // det   input pairs [c][gpix]
__device__ __align__(16) unsigned g_w2p[(size_t)1024 * C2K];  // w2 (h,l) pairs, K-order r*1280+c
__device__ __align__(16) unsigned g_rwp[(size_t)KOP * 1024];  // reweight pairs

// pack fp32 -> (fp16 hi | fp16 lo<<16); k'-order: even k' = hi, odd k' = lo
__device__ __forceinline__ unsigned packpair(float x)
{
    __half h = __float2half_rn(x);
    float r = x - __half2float(h);
    __half l = __float2half_rn(r);
    return ((unsigned)__half_as_ushort(l) << 16) | (unsigned)__half_as_ushort(h);
}

// ---------------- cp.async helpers ----------------
__device__ __forceinline__ void cp16(void* smem, const void* g)
{
    unsigned sa = (unsigned)__cvta_generic_to_shared(smem);
    asm volatile("cp.async.cg.shared.global [%0], [%1], 16;\n" :: "r"(sa), "l"(g));
}
__device__ __forceinline__ void cp_commit() { asm volatile("cp.async.commit_group;\n"); }
__device__ __forceinline__ void cp_wait0()  { asm volatile("cp.async.wait_group 0;\n"); }

// ---------------- prep: BN fold, transposes, fp16 pair packing --------------
__global__ void prep_kernel(const float* __restrict__ w1,
                            const float* __restrict__ g1, const float* __restrict__ b1,
                            const float* __restrict__ m1, const float* __restrict__ v1,
                            const float* __restrict__ g2, const float* __restrict__ b2,
                            const float* __restrict__ m2, const float* __restrict__ v2,
                            const float* __restrict__ rw, const float* __restrict__ w2)
{
    long long i = (long long)blockIdx.x * blockDim.x + threadIdx.x;
    if (i < (long long)1024 * C2K) {
        // dest-indexed: i = co*C2K + r*1280 + c  <- src co*C2K + c*9 + r
        int co = (int)(i / C2K);
        int t  = (int)(i - (long long)co * C2K);
        int r  = t / C2IN;
        int c  = t - r * C2IN;
        g_w2p[i] = packpair(w2[(size_t)co * C2K + c * 9 + r]);
    }
    if (i < (long long)KOP * 1024) {
        int m = (int)(i >> 10), c = (int)(i & 1023);
        g_rwp[i] = packpair((m < KO) ? rw[m * 1025 + c] : 0.f);
    }
    if (i < 512 * 64) {
        int k = (int)(i >> 6), co = (int)(i & 63);
        g_w1t[i] = w1[co * 512 + k];
    }
    if (i < KO)   g_cb[i] = rw[i * 1025 + 1024];
    if (i < 64)   { float s = g1[i] * rsqrtf(v1[i] + BNEPS); g_s1[i] = s; g_h1[i] = b1[i] - m1[i] * s; }
    if (i < 1024) { float s = g2[i] * rsqrtf(v2[i] + BNEPS); g_s2[i] = s; g_h2[i] = b2[i] - m2[i] * s; }
}

// ---------------- feat0 -> g_xp channels 256..1279 ----------------
__global__ void feat0_split(const float* __restrict__ feat0)
{
    long long i = (long long)blockIdx.x * blockDim.x + threadIdx.x;
    if (i < (long long)NB * 1024 * HW) {
        int hw = (int)(i % HW);
        long long t = i / HW;
        int c = (int)(t & 1023);
        int b = (int)(t >> 10);
        g_xp[(size_t)(256 + c) * NPIX + b * HW + hw] = packpair(feat0[i]);
    }
}

// ---------------- conv1 (1x1, 512->64) + BN + leaky + reorg(2) --------------
__global__ __launch_bounds__(256) void conv1_kernel(const float* __restrict__ feat1)
{
    __shared__ __align__(16) float s_in[512][16];
    __shared__ float s_w[64][64];

    const int b    = blockIdx.y;
    const int base = blockIdx.x * 16;
    const float* f = feat1 + (size_t)b * 512 * 1444;

    for (int idx = threadIdx.x; idx < 512 * 16; idx += 256) {
        int p = idx & 15, k = idx >> 4;
        int pix = base + p;
        s_in[k][p] = (pix < 1444) ? f[k * 1444 + pix] : 0.f;
    }

    const int co = threadIdx.x & 63;
    const int pq = threadIdx.x >> 6;
    float acc[4] = {0.f, 0.f, 0.f, 0.f};

    for (int kc = 0; kc < 512; kc += 64) {
        __syncthreads();
        for (int idx = threadIdx.x; idx < 64 * 64; idx += 256)
            s_w[idx >> 6][idx & 63] = g_w1t[(kc + (idx >> 6)) * 64 + (idx & 63)];
        __syncthreads();
        #pragma unroll
        for (int kk = 0; kk < 64; kk++) {
            float  w = s_w[kk][co];
            float4 v = *(const float4*)&s_in[kc + kk][pq * 4];
            acc[0] += v.x * w; acc[1] += v.y * w;
            acc[2] += v.z * w; acc[3] += v.w * w;
        }
    }

    const float s = g_s1[co], hh = g_h1[co];
    #pragma unroll
    for (int j = 0; j < 4; j++) {
        int pix = base + pq * 4 + j;
        if (pix < 1444) {
            float y = acc[j] * s + hh;
            y = (y > 0.f) ? y : LEAK * y;
            int h38 = pix / 38, w38 = pix - h38 * 38;
            int cc  = ((h38 & 1) * 2 + (w38 & 1)) * 64 + co;
            int gp  = b * HW + (h38 >> 1) * H19 + (w38 >> 1);
            g_xp[(size_t)cc * NPIX + gp] = packpair(y);
        }
    }
}

// ---------------- mma.sync helper (fp16, fp32 accum) -------------------------
__device__ __forceinline__ void mma16816(float* d, const unsigned* a, const unsigned* b)
{
    asm volatile(
        "mma.sync.aligned.m16n8k16.row.col.f32.f16.f16.f32 "
        "{%0,%1,%2,%3},{%4,%5,%6,%7},{%8,%9},{%0,%1,%2,%3};"
        : "+f"(d[0]), "+f"(d[1]), "+f"(d[2]), "+f"(d[3])
        : "r"(a[0]), "r"(a[1]), "r"(a[2]), "r"(a[3]), "r"(b[0]), "r"(b[1]));
}

// plain GEMM over K'=64 (two 32-k' chunks), 64 MMAs per warp
__device__ __forceinline__ void mma_tile(const unsigned* A0, const unsigned* A1,
                                         const unsigned* B0, const unsigned* B1,
                                         int wm, int wn, int gid, int tig,
                                         float acc[4][4][4])
{
    #pragma unroll
    for (int ch = 0; ch < 2; ch++) {
        const unsigned* Ac = ch ? A1 : A0;
        const unsigned* Bc = ch ? B1 : B0;
        #pragma unroll
        for (int kk = 0; kk < 2; kk++) {
            const int koff = kk * 8;
            unsigned b[4][2];
            #pragma unroll
            for (int ni = 0; ni < 4; ni++) {
                int col = (wn * 32 + ni * 8 + gid) * SROW + koff + tig;
                b[ni][0] = Bc[col]; b[ni][1] = Bc[col + 4];
            }
            #pragma unroll
            for (int mi = 0; mi < 4; mi++) {
                int r0 = (wm * 64 + mi * 16 + gid) * SROW + koff + tig;
                int r1 = r0 + 8 * SROW;
                unsigned a[4] = {Ac[r0], Ac[r1], Ac[r0 + 4], Ac[r1 + 4]};
                #pragma unroll
                for (int ni = 0; ni < 4; ni++)
                    mma16816(acc[mi][ni], a, b[ni]);
            }
        }
    }
}

// ---------------- conv2 (implicit GEMM, fp16 K-doubled, pipelined) ----------
__global__ __launch_bounds__(256, 2) void conv2_mma()
{
    extern __shared__ unsigned sm[];

    const int tid  = threadIdx.x;
    const int lane = tid & 31;
    const int w    = tid >> 5;
    const int gid  = lane >> 2, tig = lane & 3;
    const int wm   = w >> 2,    wn  = w & 3;

    const int co0 = blockIdx.y * 128;
    const int n0  = blockIdx.x * 128;

    // ---- B gather state ----
    const int bpx  = tid >> 1;
    const int kq   = (tid & 1) * 16;    // which 16 orig-k of the 32-k iter
    const int pixg = n0 + bpx;
    const bool px_ok = (pixg < NPIX);
    int sp_base = 0;
    unsigned vmask = 0;
    if (px_ok) {
        int bimg = pixg / HW;
        int pix  = pixg - bimg * HW;
        int oh = pix / H19, ow = pix - oh * H19;
        sp_base = bimg * HW + pix;
        #pragma unroll
        for (int r = 0; r < 9; r++) {
            int ih = oh + r / 3 - 1, iw = ow + r % 3 - 1;
            if ((unsigned)ih < 19u && (unsigned)iw < 19u) vmask |= 1u << r;
        }
    }
    int cB = kq, rB = 0;                // k-order: k = r*1280 + c

    // ---- A cp.async mapping: per thread 4x16B per iter ----
    const int arow  = tid >> 1;
    const int ahalf = tid & 1;
    const unsigned* ap = g_w2p + (size_t)(co0 + arow) * C2K + ahalf * 8;
    const int adst = arow * SROW + ahalf * 8;
    // B store base (16B-aligned)
    const int bdst = (kq ? BH1 : BH0) + bpx * SROW;

    float acc[4][4][4];
    #pragma unroll
    for (int mi = 0; mi < 4; mi++)
        #pragma unroll
        for (int ni = 0; ni < 4; ni++)
            #pragma unroll
            for (int e = 0; e < 4; e++) acc[mi][ni][e] = 0.f;

    unsigned fv[16];
    auto gatherB = [&](unsigned* dst) {
        bool val = px_ok && ((vmask >> rB) & 1u);
        int dy  = (rB * 11) >> 5;
        int off = dy * H19 + (rB - dy * 3) - 20;
        const unsigned* p = g_xp + (size_t)cB * NPIX + (sp_base + off);
        #pragma unroll
        for (int i = 0; i < 16; i++)
            dst[i] = val ? p[(size_t)i * NPIX] : 0u;
        cB += 32;
        if (cB >= C2IN) { cB -= C2IN; ++rB; }
    };
    auto loadA = [&](unsigned* stage, int it) {
        const unsigned* src = ap + it * 32;
        cp16(stage + AH0 + adst,     src);
        cp16(stage + AH0 + adst + 4, src + 4);
        cp16(stage + AH1 + adst,     src + 16);
        cp16(stage + AH1 + adst + 4, src + 20);
    };

    loadA(sm, 0);
    cp_commit();
    gatherB(fv);

    const int NIT = C2K / 32;   // 360
    int s = 0;
    for (int it = 0; it < NIT; it++) {
        unsigned* base = sm + s * STG;
        {   // store B regs -> stage s (k'-order already; 4x uint4)
            uint4* bd = (uint4*)(base + bdst);
            bd[0] = make_uint4(fv[0],  fv[1],  fv[2],  fv[3]);
            bd[1] = make_uint4(fv[4],  fv[5],  fv[6],  fv[7]);
            bd[2] = make_uint4(fv[8],  fv[9],  fv[10], fv[11]);
            bd[3] = make_uint4(fv[12], fv[13], fv[14], fv[15]);
        }
        cp_wait0();
        __syncthreads();

        if (it + 1 < NIT) {
            loadA(sm + (s ^ 1) * STG, it + 1);
            cp_commit();
            gatherB(fv);    // overlaps MMAs below
        }

        mma_tile(base + AH0, base + AH1, base + BH0, base + BH1,
                 wm, wn, gid, tig, acc);
        s ^= 1;
    }

    // epilogue: BN + leaky -> g_prep pairs [co][gpix]
    #pragma unroll
    for (int mi = 0; mi < 4; mi++) {
        int coA = co0 + wm * 64 + mi * 16 + gid;
        int coB = coA + 8;
        float sA = g_s2[coA], hA = g_h2[coA];
        float sB = g_s2[coB], hB = g_h2[coB];
        #pragma unroll
        for (int ni = 0; ni < 4; ni++) {
            int pg = n0 + wn * 32 + ni * 8 + 2 * tig;
            #pragma unroll
            for (int e = 0; e < 2; e++) {
                int p = pg + e;
                if (p < NPIX) {
                    float y = acc[mi][ni][e] * sA + hA;
                    y = (y > 0.f) ? y : LEAK * y;
                    g_prep[(size_t)coA * NPIX + p] = packpair(y);
                    float z = acc[mi][ni][2 + e] * sB + hB;
                    z = (z > 0.f) ? z : LEAK * z;
                    g_prep[(size_t)coB * NPIX + p] = packpair(z);
                }
            }
        }
    }
}

// ---------------- det head GEMM (fp16 K-doubled, pipelined) ------------------
__global__ __launch_bounds__(256, 2) void det_mma(float* __restrict__ out)
{
    extern __shared__ unsigned sm[];

    const int tid  = threadIdx.x;
    const int lane = tid & 31;
    const int w    = tid >> 5;
    const int gid  = lane >> 2, tig = lane & 3;
    const int wm   = w >> 2,    wn  = w & 3;

    const int m0 = blockIdx.y * 128;
    const int n0 = blockIdx.x * 128;

    const int bpx  = tid >> 1;
    const int kq   = (tid & 1) * 16;
    const int pixg = n0 + bpx;
    const bool px_ok = (pixg < NPIX);
    const unsigned* pb = g_prep + (size_t)kq * NPIX + (px_ok ? pixg : 0);

    const int arow  = tid >> 1;
    const int ahalf = tid & 1;
    const unsigned* ap = g_rwp + (size_t)(m0 + arow) * 1024 + ahalf * 8;
    const int adst = arow * SROW + ahalf * 8;
    const int bdst = (kq ? BH1 : BH0) + bpx * SROW;

    float acc[4][4][4];
    #pragma unroll
    for (int mi = 0; mi < 4; mi++)
        #pragma unroll
        for (int ni = 0; ni < 4; ni++)
            #pragma unroll
            for (int e = 0; e < 4; e++) acc[mi][ni][e] = 0.f;

    unsigned fv[16];
    auto gatherB = [&](unsigned* dst, int k0) {
        const unsigned* p = pb + (size_t)k0 * NPIX;
        #pragma unroll
        for (int i = 0; i < 16; i++)
            dst[i] = px_ok ? p[(size_t)i * NPIX] : 0u;
    };
    auto loadA = [&](unsigned* stage, int it) {
        const unsigned* src = ap + it * 32;
        cp16(stage + AH0 + adst,     src);
        cp16(stage + AH0 + adst + 4, src + 4);
        cp16(stage + AH1 + adst,     src + 16);
        cp16(stage + AH1 + adst + 4, src + 20);
    };

    loadA(sm, 0);
    cp_commit();
    gatherB(fv, 0);

    const int NIT = 1024 / 32;   // 32
    int s = 0;
    for (int it = 0; it < NIT; it++) {
        unsigned* base = sm + s * STG;
        {
            uint4* bd = (uint4*)(base + bdst);
            bd[0] = make_uint4(fv[0],  fv[1],  fv[2],  fv[3]);
            bd[1] = make_uint4(fv[4],  fv[5],  fv[6],  fv[7]);
            bd[2] = make_uint4(fv[8],  fv[9],  fv[10], fv[11]);
            bd[3] = make_uint4(fv[12], fv[13], fv[14], fv[15]);
        }
        cp_wait0();
        __syncthreads();

        if (it + 1 < NIT) {
            loadA(sm + (s ^ 1) * STG, it + 1);
            cp_commit();
            gatherB(fv, (it + 1) * 32);
        }

        mma_tile(base + AH0, base + AH1, base + BH0, base + BH1,
                 wm, wn, gid, tig, acc);
        s ^= 1;
    }

    #pragma unroll
    for (int mi = 0; mi < 4; mi++) {
        int mA = m0 + wm * 64 + mi * 16 + gid;
        int mB = mA + 8;
        float cA = (mA < KO) ? g_cb[mA] : 0.f;
        float cB2 = (mB < KO) ? g_cb[mB] : 0.f;
        #pragma unroll
        for (int ni = 0; ni < 4; ni++) {
            int pg = n0 + wn * 32 + ni * 8 + 2 * tig;
            #pragma unroll
            for (int e = 0; e < 2; e++) {
                int p = pg + e;
                if (p < NPIX) {
                    int b = p / HW, pp = p - b * HW;
                    if (mA < KO)
                        out[((size_t)b * KO + mA) * HW + pp] = acc[mi][ni][e] + cA;
                    if (mB < KO)
                        out[((size_t)b * KO + mB) * HW + pp] = acc[mi][ni][2 + e] + cB2;
                }
            }
        }
    }
}

// ---------------- launch ----------------------------------------------------
extern "C" void kernel_launch(void* const* d_in, const int* in_sizes, int n_in,
                              void* d_out, int out_size)
{
    const float* feat0 = (const float*)d_in[0];
    const float* feat1 = (const float*)d_in[1];
    const float* w1    = (const float*)d_in[2];
    const float* g1    = (const float*)d_in[3];
    const float* b1    = (const float*)d_in[4];
    const float* m1    = (const float*)d_in[5];
    const float* v1    = (const float*)d_in[6];
    const float* w2    = (const float*)d_in[7];
    const float* g2    = (const float*)d_in[8];
    const float* b2    = (const float*)d_in[9];
    const float* m2    = (const float*)d_in[10];
    const float* v2    = (const float*)d_in[11];
    const float* rw    = (const float*)d_in[12];
    float* out = (float*)d_out;

    cudaFuncSetAttribute(conv2_mma, cudaFuncAttributeMaxDynamicSharedMemorySize, SMEMB);
    cudaFuncSetAttribute(det_mma,   cudaFuncAttributeMaxDynamicSharedMemorySize, SMEMB);

    prep_kernel<<<46080, 256>>>(w1, g1, b1, m1, v1, g2, b2, m2, v2, rw, w2);
    feat0_split<<<92416, 256>>>(feat0);
    conv1_kernel<<<dim3(91, NB), 256>>>(feat1);
    conv2_mma<<<dim3(181, 8), 256, SMEMB>>>();
    det_mma  <<<dim3(181, 5), 256, SMEMB>>>(out);
}